// round 15
// baseline (speedup 1.0000x reference)
#include <cuda_runtime.h>
#include <cuda_fp16.h>
#include <cstdint>
#include <math.h>

// ---------------- problem dims -------------------------------------------------
static constexpr int BATCH = 2048;
static constexpr int SEQ   = 64;
static constexpr int DIN   = 512;
static constexpr int HID   = 1024;
static constexpr int N3    = 3 * HID;      // 3072
static constexpr int MT    = BATCH * SEQ;  // 131072

static constexpr int BN = 192;             // (32f|32g|32h)x2 group
static constexpr int BK = 64;              // 128 B per smem row

// asymmetric staging: A double-buffered (16 KB x2), B triple-buffered (24 KB x3)
// = 104 KB per CTA -> 2 CTAs/SM (208 KB <= 228 KB)
static constexpr int A_STAGE = 128 * 128;              // 16 KB (BM=128)
static constexpr int B_STAGE = BN * 128;               // 24 KB
static constexpr int SMEM_TOTAL = 2 * A_STAGE + 3 * B_STAGE;   // 106496

// ---------------- device scratch -------------------------------------------------
// t-major: Xt[(t*BATCH + b)*DIN + d], U[(t*BATCH + b)*N3 + n]
__device__ __align__(128) __half g_Xh[(size_t)MT * DIN];
__device__ __align__(128) __half g_U [(size_t)MT * N3];
__device__ __align__(128) __half g_Wk[(size_t)N3 * DIN];
__device__ __align__(128) __half g_Wr[(size_t)N3 * HID];
__device__ __align__(128) float  g_bias[N3];
__device__ __align__(128) __half g_H[2][(size_t)BATCH * HID];

// ---------------- helpers ---------------------------------------------------------
__device__ __forceinline__ uint32_t smem_u32(const void* p) {
    uint32_t a;
    asm("{ .reg .u64 t; cvta.to.shared.u64 t, %1; cvt.u32.u64 %0, t; }" : "=r"(a) : "l"(p));
    return a;
}
__device__ __forceinline__ void cpa16(uint32_t s, const void* g) {
    asm volatile("cp.async.cg.shared.global [%0], [%1], 16;" :: "r"(s), "l"(g));
}
__device__ __forceinline__ void cp_commit() { asm volatile("cp.async.commit_group;"); }
template<int N> __device__ __forceinline__ void cp_wait() {
    asm volatile("cp.async.wait_group %0;" :: "n"(N));
}
__device__ __forceinline__ void ldm4(uint32_t* r, uint32_t a) {
    asm volatile("ldmatrix.sync.aligned.m8n8.x4.shared.b16 {%0,%1,%2,%3}, [%4];"
                 : "=r"(r[0]), "=r"(r[1]), "=r"(r[2]), "=r"(r[3]) : "r"(a));
}
__device__ __forceinline__ void mma16(float* c, const uint32_t* a, uint32_t b0, uint32_t b1) {
    asm volatile(
        "mma.sync.aligned.m16n8k16.row.col.f32.f16.f16.f32 "
        "{%0,%1,%2,%3},{%4,%5,%6,%7},{%8,%9},{%0,%1,%2,%3};"
        : "+f"(c[0]), "+f"(c[1]), "+f"(c[2]), "+f"(c[3])
        : "r"(a[0]), "r"(a[1]), "r"(a[2]), "r"(a[3]), "r"(b0), "r"(b1));
}

// ---------------- weight repack (rows grouped (32f|32g|32h)x2 per 192) ------------
__global__ void repack_k(const float* __restrict__ Wf, const float* __restrict__ bf,
                         const float* __restrict__ Wg, const float* __restrict__ bg,
                         const float* __restrict__ Wh, const float* __restrict__ bh,
                         __half* __restrict__ wk, __half* __restrict__ wr,
                         float* __restrict__ bias) {
    int idx = blockIdx.x * blockDim.x + threadIdx.x;
    const int CIN = DIN + HID;
    const int TOT = N3 * CIN;
    if (idx < TOT) {
        int n = idx / CIN;
        int k = idx - n * CIN;
        int gi = n / 192, rem = n % 192;
        int wh = rem / 96, rem2 = rem % 96, part = rem2 >> 5, c = rem2 & 31;
        int j = gi * 64 + wh * 32 + c;
        const float* W = (part == 0) ? Wf : (part == 1) ? Wg : Wh;
        __half v = __float2half_rn(W[(size_t)j * CIN + k]);
        if (k < DIN) wk[(size_t)n * DIN + k] = v;
        else         wr[(size_t)n * HID + (k - DIN)] = v;
    } else if (idx < TOT + N3) {
        int n = idx - TOT;
        int gi = n / 192, rem = n % 192;
        int wh = rem / 96, rem2 = rem % 96, part = rem2 >> 5, c = rem2 & 31;
        int j = gi * 64 + wh * 32 + c;
        bias[n] = ((part == 0) ? bf : (part == 1) ? bg : bh)[j];
    }
}

// x[b][t][d] (float) -> Xt[t][b][d] (half)
__global__ void cvtx_k(const float4* __restrict__ x, __half2* __restrict__ xt, int n4) {
    int i = blockIdx.x * blockDim.x + threadIdx.x;
    if (i >= n4) return;
    float4 v = x[i];
    int d4 = i & 127;                    // DIN/4 = 128
    int t  = (i >> 7) & 63;
    int b  = i >> 13;
    size_t o2 = ((size_t)(t * BATCH + b) * DIN + d4 * 4) >> 1;
    xt[o2]     = __floats2half2_rn(v.x, v.y);
    xt[o2 + 1] = __floats2half2_rn(v.z, v.w);
}

// ---------------- fp16 warp-MMA GEMM: C[M,3072] = A[M,K] @ Bw[3072,K]^T -----------
// 128 B smem rows; chunk ch of row r stored at ch ^ (r & 7): all ldmatrix and
// cp.async phases touch all 32 banks exactly once (conflict-free).
// Asymmetric pipeline: A 2-deep, B 3-deep. Per iter kt: commit [A(kt+1)] then
// [B(kt+2)]; top-of-loop cp_wait<1> completes A(kt)+B(kt) (older groups) while
// the newest B load stays in flight -> B gets 2 chunks of latency budget.
// ONE __syncthreads per K-chunk; 2 CTAs/SM.
// MODE 0: U = acc + bias (fp16, TBM x 192 tile, row stride N3).
// MODE 1: pre = acc + U (t-major, stride N3); gate-combine in regs; write h.
template<int K, int MODE, int TBM, int TTHREADS>
__global__ __launch_bounds__(TTHREADS, 2)
void lnn_gemm(const __half* __restrict__ A, const __half* __restrict__ Bw,
              __half* __restrict__ out, const __half* __restrict__ add,
              const float* __restrict__ bias) {
    constexpr int A_BY = TBM * 128;
    constexpr int B_BY = BN * 128;
    extern __shared__ __align__(1024) char smem[];
    const uint32_t sb = smem_u32(smem);
    const uint32_t aBase = sb;
    const uint32_t bBase = sb + 2 * A_BY;
    const int tid = threadIdx.x, lane = tid & 31, wid = tid >> 5;
    const int wm = wid >> 1, wn = wid & 1;
    const int bn = blockIdx.x, bm = blockIdx.y;

    const __half* Ag = A  + (size_t)bm * TBM * K;
    const __half* Bg = Bw + (size_t)bn * BN * K;

    auto load_A = [&](int s, int kt) {
        uint32_t base = aBase + s * A_BY;
#pragma unroll
        for (int i = 0; i < TBM * 8 / TTHREADS; i++) {
            int q = tid + i * TTHREADS;
            int row = q >> 3, ch = q & 7;
            int phys = ch ^ (row & 7);
            cpa16(base + row * 128 + phys * 16,
                  Ag + (size_t)row * K + kt * 64 + ch * 8);
        }
    };
    auto load_B = [&](int s, int kt) {
        uint32_t base = bBase + s * B_BY;
#pragma unroll
        for (int i = 0; i < BN * 8 / TTHREADS; i++) {
            int q = tid + i * TTHREADS;
            int row = q >> 3, ch = q & 7;
            int phys = ch ^ (row & 7);
            cpa16(base + row * 128 + phys * 16,
                  Bg + (size_t)row * K + kt * 64 + ch * 8);
        }
    };

    // fragment lane constants
    const int t4 = lane & 3, gq = lane >> 2;
    const int rowA0 = wm * 32 + (lane & 15);
    const int selA  = lane >> 4;                       // k-half chunk for A ldmatrix
    const int laneRowB = (lane & 7) + ((lane >> 4) << 3);
    const int choffB = (lane >> 3) & 1;

    float acc[2][12][4];
#pragma unroll
    for (int a = 0; a < 2; a++)
#pragma unroll
        for (int b = 0; b < 12; b++)
#pragma unroll
            for (int d = 0; d < 4; d++) acc[a][b][d] = 0.f;

    const int KT = K / BK;                 // 8 or 16 (>= 3)
    // prologue: [A0] [B0] [B1]
    load_A(0, 0); cp_commit();
    load_B(0, 0); cp_commit();
    load_B(1, 1); cp_commit();

    int bcur = 0;                          // B stage of chunk kt
    int bnxt = 2;                          // B stage for chunk kt+2

    for (int kt = 0; kt < KT; ++kt) {
        if (kt < KT - 1) { cp_wait<1>(); } else { cp_wait<0>(); }
        __syncthreads();                   // stage kt visible; stage reuse safe
        if (kt + 1 < KT) { load_A((kt + 1) & 1, kt + 1); cp_commit(); }
        if (kt + 2 < KT) {
            load_B(bnxt, kt + 2); cp_commit();
            bnxt = (bnxt == 2) ? 0 : bnxt + 1;
        }

        uint32_t ab = aBase + (kt & 1) * A_BY;
        uint32_t bb = bBase + bcur * B_BY;
        bcur = (bcur == 2) ? 0 : bcur + 1;
#pragma unroll
        for (int k2 = 0; k2 < 4; k2++) {               // 4 x k16 per 128B row
            uint32_t a0[4], a1[4];
            {
                int r = rowA0;
                uint32_t ph = (uint32_t)((k2 * 2 + selA) ^ (r & 7));
                ldm4(a0, ab + r * 128 + ph * 16);
            }
            {
                int r = rowA0 + 16;
                uint32_t ph = (uint32_t)((k2 * 2 + selA) ^ (r & 7));
                ldm4(a1, ab + r * 128 + ph * 16);
            }
#pragma unroll
            for (int nb = 0; nb < 6; nb++) {
                uint32_t b[4];
                int r = wn * 96 + nb * 16 + laneRowB;
                uint32_t ph = (uint32_t)((k2 * 2 + choffB) ^ (r & 7));
                ldm4(b, bb + r * 128 + ph * 16);
                mma16(acc[0][2 * nb],     a0, b[0], b[1]);
                mma16(acc[1][2 * nb],     a1, b[0], b[1]);
                mma16(acc[0][2 * nb + 1], a0, b[2], b[3]);
                mma16(acc[1][2 * nb + 1], a1, b[2], b[3]);
            }
        }
    }

    if (MODE == 0) {
#pragma unroll
        for (int mt = 0; mt < 2; mt++) {
            int rl = bm * TBM + wm * 32 + mt * 16 + gq, rh = rl + 8;
#pragma unroll
            for (int nt = 0; nt < 12; nt++) {
                int col = bn * BN + wn * 96 + nt * 8 + t4 * 2;
                float b0 = bias[col], b1 = bias[col + 1];
                __half2 v0 = __floats2half2_rn(acc[mt][nt][0] + b0, acc[mt][nt][1] + b1);
                __half2 v1 = __floats2half2_rn(acc[mt][nt][2] + b0, acc[mt][nt][3] + b1);
                *(__half2*)(out + (size_t)rl * N3 + col) = v0;
                *(__half2*)(out + (size_t)rh * N3 + col) = v1;
            }
        }
    } else {
        // warp owns matched f/g/h: nt 0-3 = f, 4-7 = g, 8-11 = h
        int gcb = bn * 64 + wn * 32;               // original hidden col base
        int ub  = bn * BN + wn * 96;               // U col base (repacked)
#pragma unroll
        for (int mt = 0; mt < 2; mt++) {
            int rl = bm * TBM + wm * 32 + mt * 16 + gq, rh = rl + 8;
            const __half* ul = add + (size_t)rl * N3 + ub;
            const __half* uh = add + (size_t)rh * N3 + ub;
#pragma unroll
            for (int j = 0; j < 4; j++) {
                int co = j * 8 + t4 * 2;
                float2 ufl = __half22float2(*(const __half2*)(ul + co));
                float2 ugl = __half22float2(*(const __half2*)(ul + 32 + co));
                float2 uhl = __half22float2(*(const __half2*)(ul + 64 + co));
                float2 ufh = __half22float2(*(const __half2*)(uh + co));
                float2 ugh = __half22float2(*(const __half2*)(uh + 32 + co));
                float2 uhh = __half22float2(*(const __half2*)(uh + 64 + co));
                float o0, o1, o2, o3;
                {
                    float f = acc[mt][j][0] + ufl.x, g = acc[mt][j + 4][0] + ugl.x,
                          h = acc[mt][j + 8][0] + uhl.x;
                    float gate = 1.f / (1.f + __expf(f));
                    o0 = h + gate * (g - h);
                }
                {
                    float f = acc[mt][j][1] + ufl.y, g = acc[mt][j + 4][1] + ugl.y,
                          h = acc[mt][j + 8][1] + uhl.y;
                    float gate = 1.f / (1.f + __expf(f));
                    o1 = h + gate * (g - h);
                }
                {
                    float f = acc[mt][j][2] + ufh.x, g = acc[mt][j + 4][2] + ugh.x,
                          h = acc[mt][j + 8][2] + uhh.x;
                    float gate = 1.f / (1.f + __expf(f));
                    o2 = h + gate * (g - h);
                }
                {
                    float f = acc[mt][j][3] + ufh.y, g = acc[mt][j + 4][3] + ugh.y,
                          h = acc[mt][j + 8][3] + uhh.y;
                    float gate = 1.f / (1.f + __expf(f));
                    o3 = h + gate * (g - h);
                }
                *(__half2*)(out + (size_t)rl * HID + gcb + co) = __floats2half2_rn(o0, o1);
                *(__half2*)(out + (size_t)rh * HID + gcb + co) = __floats2half2_rn(o2, o3);
            }
        }
    }
}

// ---------------- step 0 combine (h0 = 0): pre = U[t=0] ---------------------------
__global__ void combine0_k(const __half* __restrict__ U0, __half* __restrict__ h0) {
    int idx = blockIdx.x * blockDim.x + threadIdx.x;
    if (idx >= BATCH * HID) return;
    int b = idx >> 10, j = idx & (HID - 1);
    int gi = j >> 6, wh = (j >> 5) & 1, c = j & 31;
    const __half* r = U0 + (size_t)b * N3 + gi * 192 + wh * 96;
    float f = __half2float(r[c]), g = __half2float(r[32 + c]), hh = __half2float(r[64 + c]);
    float gate = 1.f / (1.f + __expf(f));
    h0[idx] = __float2half_rn(hh + gate * (g - hh));
}

// ---------------- final FC (fp32 exact) ---------------------------------------------
__global__ void final_k(const __half* __restrict__ h, const float* __restrict__ Wfc,
                        const float* __restrict__ bfc, float* __restrict__ out) {
    int b = blockIdx.x;
    float s0 = 0.f, s1 = 0.f;
    for (int j = threadIdx.x; j < HID; j += blockDim.x) {
        float hv = __half2float(h[(size_t)b * HID + j]);
        s0 += hv * Wfc[j];
        s1 += hv * Wfc[HID + j];
    }
#pragma unroll
    for (int o = 16; o > 0; o >>= 1) {
        s0 += __shfl_down_sync(0xFFFFFFFFu, s0, o);
        s1 += __shfl_down_sync(0xFFFFFFFFu, s1, o);
    }
    __shared__ float sm[2][8];
    int warp = threadIdx.x >> 5, lane = threadIdx.x & 31;
    if (lane == 0) { sm[0][warp] = s0; sm[1][warp] = s1; }
    __syncthreads();
    if (threadIdx.x == 0) {
        float t0 = 0.f, t1 = 0.f;
        int nw = blockDim.x >> 5;
        for (int w = 0; w < nw; w++) { t0 += sm[0][w]; t1 += sm[1][w]; }
        out[b * 2 + 0] = t0 + bfc[0];
        out[b * 2 + 1] = t1 + bfc[1];
    }
}

// ---------------- launch --------------------------------------------------------------
extern "C" void kernel_launch(void* const* d_in, const int* in_sizes, int n_in,
                              void* d_out, int out_size) {
    const float* x   = (const float*)d_in[0];
    const float* Wf  = (const float*)d_in[1];
    const float* bf  = (const float*)d_in[2];
    const float* Wg  = (const float*)d_in[3];
    const float* bg  = (const float*)d_in[4];
    const float* Wh  = (const float*)d_in[5];
    const float* bh  = (const float*)d_in[6];
    const float* Wfc = (const float*)d_in[7];
    const float* bfc = (const float*)d_in[8];

    __half *pXh, *pU, *pWk, *pWr, *pH;
    float *pBias;
    cudaGetSymbolAddress((void**)&pXh,  g_Xh);
    cudaGetSymbolAddress((void**)&pU,   g_U);
    cudaGetSymbolAddress((void**)&pWk,  g_Wk);
    cudaGetSymbolAddress((void**)&pWr,  g_Wr);
    cudaGetSymbolAddress((void**)&pBias,g_bias);
    cudaGetSymbolAddress((void**)&pH,   g_H);
    __half* pH0 = pH;
    __half* pH1 = pH + (size_t)BATCH * HID;

    auto urec  = lnn_gemm<HID, 1, 128, 256>;
    auto uprec = lnn_gemm<DIN, 0, 128, 256>;
    cudaFuncSetAttribute(urec,  cudaFuncAttributeMaxDynamicSharedMemorySize, SMEM_TOTAL);
    cudaFuncSetAttribute(uprec, cudaFuncAttributeMaxDynamicSharedMemorySize, SMEM_TOTAL);

    // low-priority side stream for repack + U precompute
    int loPri = 0, hiPri = 0;
    cudaDeviceGetStreamPriorityRange(&loPri, &hiPri);
    cudaStream_t s1;
    cudaStreamCreateWithPriority(&s1, cudaStreamNonBlocking, loPri);

    // fork FIRST (capture rule), then overlap cvtx (s0) with repack (s1)
    cudaEvent_t evFork;
    cudaEventCreateWithFlags(&evFork, cudaEventDisableTiming);
    cudaEventRecord(evFork, 0);
    cudaStreamWaitEvent(s1, evFork, 0);

    {
        int n4 = MT * DIN / 4;
        cvtx_k<<<(n4 + 255) / 256, 256>>>((const float4*)x, (__half2*)pXh, n4);
        int tot = N3 * (DIN + HID) + N3;
        repack_k<<<(tot + 255) / 256, 256, 0, s1>>>(Wf, bf, Wg, bg, Wh, bh,
                                                    pWk, pWr, pBias);
    }
    // two-way join
    cudaEvent_t evX, evW;
    cudaEventCreateWithFlags(&evX, cudaEventDisableTiming);
    cudaEventCreateWithFlags(&evW, cudaEventDisableTiming);
    cudaEventRecord(evX, 0);
    cudaEventRecord(evW, s1);
    cudaStreamWaitEvent(0, evW, 0);
    cudaStreamWaitEvent(s1, evX, 0);

    dim3 ugrid(N3 / BN, BATCH / 128);            // 16 x 16 = 256 CTAs per t

    // 2) prologue on stream 0: U[0], U[1]
    uprec<<<ugrid, 256, SMEM_TOTAL>>>(pXh, pWk, pU, nullptr, pBias);
    uprec<<<ugrid, 256, SMEM_TOTAL>>>(pXh + (size_t)BATCH * DIN, pWk,
                                      pU + (size_t)BATCH * N3, nullptr, pBias);

    // 3) t=0 (h0 = 0)
    combine0_k<<<(BATCH * HID) / 256, 256>>>(pU, pH0);

    // 4a) queue U[2..63] on low-priority stream, one event per step
    cudaEvent_t evU[SEQ];
    for (int t = 2; t < SEQ; t++) {
        uprec<<<ugrid, 256, SMEM_TOTAL, s1>>>(pXh + (size_t)t * BATCH * DIN, pWk,
                                              pU + (size_t)t * BATCH * N3, nullptr, pBias);
        cudaEventCreateWithFlags(&evU[t], cudaEventDisableTiming);
        cudaEventRecord(evU[t], s1);
    }

    // 4b) recurrence on stream 0; step t waits for U[t]
    for (int t = 1; t < SEQ; t++) {
        if (t >= 2) cudaStreamWaitEvent(0, evU[t], 0);
        __half* hprev = ((t - 1) & 1) ? pH1 : pH0;
        __half* hnext = (t & 1) ? pH1 : pH0;
        urec<<<dim3(N3 / BN, BATCH / 128), 256, SMEM_TOTAL>>>(
            hprev, pWr, hnext, pU + (size_t)t * BATCH * N3, nullptr);
    }

    // 5) final FC
    final_k<<<BATCH, 256>>>(pH1, Wfc, bfc, (float*)d_out);
}

// round 16
// speedup vs baseline: 1.0629x; 1.0629x over previous
#include <cuda_runtime.h>
#include <cuda_fp16.h>
#include <cstdint>
#include <math.h>

// ---------------- problem dims -------------------------------------------------
static constexpr int BATCH = 2048;
static constexpr int SEQ   = 64;
static constexpr int DIN   = 512;
static constexpr int HID   = 1024;
static constexpr int N3    = 3 * HID;      // 3072
static constexpr int MT    = BATCH * SEQ;  // 131072

static constexpr int BN = 192;             // (32f|32g|32h)x2 group
static constexpr int BK = 64;              // 128 B per smem row
static constexpr int STAGES = 2;

// both kernels: BM=128, 256 thr -> 80 KB smem, 2 CTAs/SM  (round-14 winner)
static constexpr int SMEM_REC = STAGES * (128 * 128 + BN * 128);  // 81920

// ---------------- device scratch -------------------------------------------------
// t-major: Xt[(t*BATCH + b)*DIN + d], U[(t*BATCH + b)*N3 + n]
__device__ __align__(128) __half g_Xh[(size_t)MT * DIN];
__device__ __align__(128) __half g_U [(size_t)MT * N3];
__device__ __align__(128) __half g_Wk[(size_t)N3 * DIN];
__device__ __align__(128) __half g_Wr[(size_t)N3 * HID];
__device__ __align__(128) float  g_bias[N3];
__device__ __align__(128) __half g_H[2][(size_t)BATCH * HID];

// ---------------- helpers ---------------------------------------------------------
__device__ __forceinline__ uint32_t smem_u32(const void* p) {
    uint32_t a;
    asm("{ .reg .u64 t; cvta.to.shared.u64 t, %1; cvt.u32.u64 %0, t; }" : "=r"(a) : "l"(p));
    return a;
}
__device__ __forceinline__ void cpa16(uint32_t s, const void* g) {
    asm volatile("cp.async.cg.shared.global [%0], [%1], 16;" :: "r"(s), "l"(g));
}
__device__ __forceinline__ void cp_commit() { asm volatile("cp.async.commit_group;"); }
template<int N> __device__ __forceinline__ void cp_wait() {
    asm volatile("cp.async.wait_group %0;" :: "n"(N));
}
__device__ __forceinline__ void ldm4(uint32_t* r, uint32_t a) {
    asm volatile("ldmatrix.sync.aligned.m8n8.x4.shared.b16 {%0,%1,%2,%3}, [%4];"
                 : "=r"(r[0]), "=r"(r[1]), "=r"(r[2]), "=r"(r[3]) : "r"(a));
}
__device__ __forceinline__ void mma16(float* c, const uint32_t* a, uint32_t b0, uint32_t b1) {
    asm volatile(
        "mma.sync.aligned.m16n8k16.row.col.f32.f16.f16.f32 "
        "{%0,%1,%2,%3},{%4,%5,%6,%7},{%8,%9},{%0,%1,%2,%3};"
        : "+f"(c[0]), "+f"(c[1]), "+f"(c[2]), "+f"(c[3])
        : "r"(a[0]), "r"(a[1]), "r"(a[2]), "r"(a[3]), "r"(b0), "r"(b1));
}

// ---------------- weight repack (rows grouped (32f|32g|32h)x2 per 192) ------------
__global__ void repack_k(const float* __restrict__ Wf, const float* __restrict__ bf,
                         const float* __restrict__ Wg, const float* __restrict__ bg,
                         const float* __restrict__ Wh, const float* __restrict__ bh,
                         __half* __restrict__ wk, __half* __restrict__ wr,
                         float* __restrict__ bias) {
    int idx = blockIdx.x * blockDim.x + threadIdx.x;
    const int CIN = DIN + HID;
    const int TOT = N3 * CIN;
    if (idx < TOT) {
        int n = idx / CIN;
        int k = idx - n * CIN;
        int gi = n / 192, rem = n % 192;
        int wh = rem / 96, rem2 = rem % 96, part = rem2 >> 5, c = rem2 & 31;
        int j = gi * 64 + wh * 32 + c;
        const float* W = (part == 0) ? Wf : (part == 1) ? Wg : Wh;
        __half v = __float2half_rn(W[(size_t)j * CIN + k]);
        if (k < DIN) wk[(size_t)n * DIN + k] = v;
        else         wr[(size_t)n * HID + (k - DIN)] = v;
    } else if (idx < TOT + N3) {
        int n = idx - TOT;
        int gi = n / 192, rem = n % 192;
        int wh = rem / 96, rem2 = rem % 96, part = rem2 >> 5, c = rem2 & 31;
        int j = gi * 64 + wh * 32 + c;
        bias[n] = ((part == 0) ? bf : (part == 1) ? bg : bh)[j];
    }
}

// x[b][t][d] (float) -> Xt[t][b][d] (half), for t in [t0, t0+tcnt)
__global__ void cvtx_k(const float4* __restrict__ x, __half2* __restrict__ xt,
                       int t0, int tcnt) {
    int i = blockIdx.x * blockDim.x + threadIdx.x;
    int total = BATCH * tcnt * (DIN / 4);
    if (i >= total) return;
    int d4 = i & 127;                    // DIN/4 = 128
    int r  = i >> 7;                     // b * tcnt + tt
    int tt = r % tcnt;
    int b  = r / tcnt;
    int t  = t0 + tt;
    float4 v = x[((size_t)b * SEQ + t) * 128 + d4];
    size_t o2 = ((size_t)(t * BATCH + b) * DIN + d4 * 4) >> 1;
    xt[o2]     = __floats2half2_rn(v.x, v.y);
    xt[o2 + 1] = __floats2half2_rn(v.z, v.w);
}

// ---------------- fp16 warp-MMA GEMM: C[M,3072] = A[M,K] @ Bw[3072,K]^T -----------
// 128 B smem rows; chunk ch of row r stored at ch ^ (r & 7): all ldmatrix and
// cp.async phases touch all 32 banks exactly once (conflict-free).
// 2-stage double buffer, ONE __syncthreads per K-chunk; 2 CTAs/SM.
// MODE 0: U = acc + bias (fp16, TBM x 192 tile, row stride N3).
// MODE 1: pre = acc + U (t-major, stride N3); gate-combine in regs; write h.
template<int K, int MODE, int TBM, int TTHREADS>
__global__ __launch_bounds__(TTHREADS, 2)
void lnn_gemm(const __half* __restrict__ A, const __half* __restrict__ Bw,
              __half* __restrict__ out, const __half* __restrict__ add,
              const float* __restrict__ bias) {
    constexpr int A_BY  = TBM * 128;
    constexpr int ST_BY = A_BY + BN * 128;
    extern __shared__ __align__(1024) char smem[];
    const uint32_t sb = smem_u32(smem);
    const int tid = threadIdx.x, lane = tid & 31, wid = tid >> 5;
    const int wm = wid >> 1, wn = wid & 1;
    const int bn = blockIdx.x, bm = blockIdx.y;

    const __half* Ag = A  + (size_t)bm * TBM * K;
    const __half* Bg = Bw + (size_t)bn * BN * K;

    auto load_stage = [&](int s, int kt) {
        uint32_t base = sb + s * ST_BY;
#pragma unroll
        for (int i = 0; i < TBM * 8 / TTHREADS; i++) {   // A chunks
            int q = tid + i * TTHREADS;
            int row = q >> 3, ch = q & 7;
            int phys = ch ^ (row & 7);
            cpa16(base + row * 128 + phys * 16,
                  Ag + (size_t)row * K + kt * 64 + ch * 8);
        }
#pragma unroll
        for (int i = 0; i < BN * 8 / TTHREADS; i++) {    // B chunks
            int q = tid + i * TTHREADS;
            int row = q >> 3, ch = q & 7;
            int phys = ch ^ (row & 7);
            cpa16(base + A_BY + row * 128 + phys * 16,
                  Bg + (size_t)row * K + kt * 64 + ch * 8);
        }
    };

    // fragment lane constants
    const int t4 = lane & 3, gq = lane >> 2;
    const int rowA0 = wm * 32 + (lane & 15);
    const int selA  = lane >> 4;                       // k-half chunk for A ldmatrix
    const int laneRowB = (lane & 7) + ((lane >> 4) << 3);
    const int choffB = (lane >> 3) & 1;

    float acc[2][12][4];
#pragma unroll
    for (int a = 0; a < 2; a++)
#pragma unroll
        for (int b = 0; b < 12; b++)
#pragma unroll
            for (int d = 0; d < 4; d++) acc[a][b][d] = 0.f;

    const int KT = K / BK;
    load_stage(0, 0); cp_commit();

    for (int kt = 0; kt < KT; ++kt) {
        cp_wait<0>();
        __syncthreads();               // stage kt ready; prev compute done by all
        if (kt + 1 < KT) { load_stage((kt + 1) & 1, kt + 1); cp_commit(); }

        uint32_t ab = sb + (kt & 1) * ST_BY;
        uint32_t bb = ab + A_BY;
#pragma unroll
        for (int k2 = 0; k2 < 4; k2++) {               // 4 x k16 per 128B row
            uint32_t a0[4], a1[4];
            {
                int r = rowA0;
                uint32_t ph = (uint32_t)((k2 * 2 + selA) ^ (r & 7));
                ldm4(a0, ab + r * 128 + ph * 16);
            }
            {
                int r = rowA0 + 16;
                uint32_t ph = (uint32_t)((k2 * 2 + selA) ^ (r & 7));
                ldm4(a1, ab + r * 128 + ph * 16);
            }
#pragma unroll
            for (int nb = 0; nb < 6; nb++) {
                uint32_t b[4];
                int r = wn * 96 + nb * 16 + laneRowB;
                uint32_t ph = (uint32_t)((k2 * 2 + choffB) ^ (r & 7));
                ldm4(b, bb + r * 128 + ph * 16);
                mma16(acc[0][2 * nb],     a0, b[0], b[1]);
                mma16(acc[1][2 * nb],     a1, b[0], b[1]);
                mma16(acc[0][2 * nb + 1], a0, b[2], b[3]);
                mma16(acc[1][2 * nb + 1], a1, b[2], b[3]);
            }
        }
    }

    if (MODE == 0) {
#pragma unroll
        for (int mt = 0; mt < 2; mt++) {
            int rl = bm * TBM + wm * 32 + mt * 16 + gq, rh = rl + 8;
#pragma unroll
            for (int nt = 0; nt < 12; nt++) {
                int col = bn * BN + wn * 96 + nt * 8 + t4 * 2;
                float b0 = bias[col], b1 = bias[col + 1];
                __half2 v0 = __floats2half2_rn(acc[mt][nt][0] + b0, acc[mt][nt][1] + b1);
                __half2 v1 = __floats2half2_rn(acc[mt][nt][2] + b0, acc[mt][nt][3] + b1);
                *(__half2*)(out + (size_t)rl * N3 + col) = v0;
                *(__half2*)(out + (size_t)rh * N3 + col) = v1;
            }
        }
    } else {
        // warp owns matched f/g/h: nt 0-3 = f, 4-7 = g, 8-11 = h
        int gcb = bn * 64 + wn * 32;               // original hidden col base
        int ub  = bn * BN + wn * 96;               // U col base (repacked)
#pragma unroll
        for (int mt = 0; mt < 2; mt++) {
            int rl = bm * TBM + wm * 32 + mt * 16 + gq, rh = rl + 8;
            const __half* ul = add + (size_t)rl * N3 + ub;
            const __half* uh = add + (size_t)rh * N3 + ub;
#pragma unroll
            for (int j = 0; j < 4; j++) {
                int co = j * 8 + t4 * 2;
                float2 ufl = __half22float2(*(const __half2*)(ul + co));
                float2 ugl = __half22float2(*(const __half2*)(ul + 32 + co));
                float2 uhl = __half22float2(*(const __half2*)(ul + 64 + co));
                float2 ufh = __half22float2(*(const __half2*)(uh + co));
                float2 ugh = __half22float2(*(const __half2*)(uh + 32 + co));
                float2 uhh = __half22float2(*(const __half2*)(uh + 64 + co));
                float o0, o1, o2, o3;
                {
                    float f = acc[mt][j][0] + ufl.x, g = acc[mt][j + 4][0] + ugl.x,
                          h = acc[mt][j + 8][0] + uhl.x;
                    float gate = 1.f / (1.f + __expf(f));
                    o0 = h + gate * (g - h);
                }
                {
                    float f = acc[mt][j][1] + ufl.y, g = acc[mt][j + 4][1] + ugl.y,
                          h = acc[mt][j + 8][1] + uhl.y;
                    float gate = 1.f / (1.f + __expf(f));
                    o1 = h + gate * (g - h);
                }
                {
                    float f = acc[mt][j][2] + ufh.x, g = acc[mt][j + 4][2] + ugh.x,
                          h = acc[mt][j + 8][2] + uhh.x;
                    float gate = 1.f / (1.f + __expf(f));
                    o2 = h + gate * (g - h);
                }
                {
                    float f = acc[mt][j][3] + ufh.y, g = acc[mt][j + 4][3] + ugh.y,
                          h = acc[mt][j + 8][3] + uhh.y;
                    float gate = 1.f / (1.f + __expf(f));
                    o3 = h + gate * (g - h);
                }
                *(__half2*)(out + (size_t)rl * HID + gcb + co) = __floats2half2_rn(o0, o1);
                *(__half2*)(out + (size_t)rh * HID + gcb + co) = __floats2half2_rn(o2, o3);
            }
        }
    }
}

// ---------------- step 0 combine (h0 = 0): pre = U[t=0] ---------------------------
__global__ void combine0_k(const __half* __restrict__ U0, __half* __restrict__ h0) {
    int idx = blockIdx.x * blockDim.x + threadIdx.x;
    if (idx >= BATCH * HID) return;
    int b = idx >> 10, j = idx & (HID - 1);
    int gi = j >> 6, wh = (j >> 5) & 1, c = j & 31;
    const __half* r = U0 + (size_t)b * N3 + gi * 192 + wh * 96;
    float f = __half2float(r[c]), g = __half2float(r[32 + c]), hh = __half2float(r[64 + c]);
    float gate = 1.f / (1.f + __expf(f));
    h0[idx] = __float2half_rn(hh + gate * (g - hh));
}

// ---------------- final FC (fp32 exact) ---------------------------------------------
__global__ void final_k(const __half* __restrict__ h, const float* __restrict__ Wfc,
                        const float* __restrict__ bfc, float* __restrict__ out) {
    int b = blockIdx.x;
    float s0 = 0.f, s1 = 0.f;
    for (int j = threadIdx.x; j < HID; j += blockDim.x) {
        float hv = __half2float(h[(size_t)b * HID + j]);
        s0 += hv * Wfc[j];
        s1 += hv * Wfc[HID + j];
    }
#pragma unroll
    for (int o = 16; o > 0; o >>= 1) {
        s0 += __shfl_down_sync(0xFFFFFFFFu, s0, o);
        s1 += __shfl_down_sync(0xFFFFFFFFu, s1, o);
    }
    __shared__ float sm[2][8];
    int warp = threadIdx.x >> 5, lane = threadIdx.x & 31;
    if (lane == 0) { sm[0][warp] = s0; sm[1][warp] = s1; }
    __syncthreads();
    if (threadIdx.x == 0) {
        float t0 = 0.f, t1 = 0.f;
        int nw = blockDim.x >> 5;
        for (int w = 0; w < nw; w++) { t0 += sm[0][w]; t1 += sm[1][w]; }
        out[b * 2 + 0] = t0 + bfc[0];
        out[b * 2 + 1] = t1 + bfc[1];
    }
}

// ---------------- launch --------------------------------------------------------------
extern "C" void kernel_launch(void* const* d_in, const int* in_sizes, int n_in,
                              void* d_out, int out_size) {
    const float* x   = (const float*)d_in[0];
    const float* Wf  = (const float*)d_in[1];
    const float* bf  = (const float*)d_in[2];
    const float* Wg  = (const float*)d_in[3];
    const float* bg  = (const float*)d_in[4];
    const float* Wh  = (const float*)d_in[5];
    const float* bh  = (const float*)d_in[6];
    const float* Wfc = (const float*)d_in[7];
    const float* bfc = (const float*)d_in[8];

    __half *pXh, *pU, *pWk, *pWr, *pH;
    float *pBias;
    cudaGetSymbolAddress((void**)&pXh,  g_Xh);
    cudaGetSymbolAddress((void**)&pU,   g_U);
    cudaGetSymbolAddress((void**)&pWk,  g_Wk);
    cudaGetSymbolAddress((void**)&pWr,  g_Wr);
    cudaGetSymbolAddress((void**)&pBias,g_bias);
    cudaGetSymbolAddress((void**)&pH,   g_H);
    __half* pH0 = pH;
    __half* pH1 = pH + (size_t)BATCH * HID;

    auto urec  = lnn_gemm<HID, 1, 128, 256>;
    auto uprec = lnn_gemm<DIN, 0, 128, 256>;
    cudaFuncSetAttribute(urec,  cudaFuncAttributeMaxDynamicSharedMemorySize, SMEM_REC);
    cudaFuncSetAttribute(uprec, cudaFuncAttributeMaxDynamicSharedMemorySize, SMEM_REC);

    // low-priority side stream for bulk cvtx + U precompute
    int loPri = 0, hiPri = 0;
    cudaDeviceGetStreamPriorityRange(&loPri, &hiPri);
    cudaStream_t s1;
    cudaStreamCreateWithPriority(&s1, cudaStreamNonBlocking, loPri);

    // capture-legal fork FIRST
    cudaEvent_t evFork;
    cudaEventCreateWithFlags(&evFork, cudaEventDisableTiming);
    cudaEventRecord(evFork, 0);
    cudaStreamWaitEvent(s1, evFork, 0);

    // s0: convert ONLY t=0,1 (critical path), then repack weights
    {
        int tot01 = BATCH * 2 * (DIN / 4);
        cvtx_k<<<(tot01 + 255) / 256, 256>>>((const float4*)x, (__half2*)pXh, 0, 2);
        int tot = N3 * (DIN + HID) + N3;
        repack_k<<<(tot + 255) / 256, 256>>>(Wf, bf, Wg, bg, Wh, bh,
                                             pWk, pWr, pBias);
    }
    // s1: bulk convert t=2..63 concurrently (bandwidth work vs s0 compute)
    {
        int totR = BATCH * (SEQ - 2) * (DIN / 4);
        cvtx_k<<<(totR + 255) / 256, 256, 0, s1>>>((const float4*)x, (__half2*)pXh,
                                                   2, SEQ - 2);
    }
    // join: s1's U queue needs Wk/bias from s0 (its own cvtx is stream-ordered)
    cudaEvent_t evW;
    cudaEventCreateWithFlags(&evW, cudaEventDisableTiming);
    cudaEventRecord(evW, 0);
    cudaStreamWaitEvent(s1, evW, 0);

    dim3 ugrid(N3 / BN, BATCH / 128);            // 16 x 16 = 256 CTAs per t

    // s0: U[0], U[1] (need only Xt[0..1] + Wk, both s0-ordered)
    uprec<<<ugrid, 256, SMEM_REC>>>(pXh, pWk, pU, nullptr, pBias);
    uprec<<<ugrid, 256, SMEM_REC>>>(pXh + (size_t)BATCH * DIN, pWk,
                                    pU + (size_t)BATCH * N3, nullptr, pBias);

    // t=0 (h0 = 0)
    combine0_k<<<(BATCH * HID) / 256, 256>>>(pU, pH0);

    // s1: queue U[2..63], one event per step
    cudaEvent_t evU[SEQ];
    for (int t = 2; t < SEQ; t++) {
        uprec<<<ugrid, 256, SMEM_REC, s1>>>(pXh + (size_t)t * BATCH * DIN, pWk,
                                            pU + (size_t)t * BATCH * N3, nullptr, pBias);
        cudaEventCreateWithFlags(&evU[t], cudaEventDisableTiming);
        cudaEventRecord(evU[t], s1);
    }

    // s0: recurrence; step t waits for U[t]
    for (int t = 1; t < SEQ; t++) {
        if (t >= 2) cudaStreamWaitEvent(0, evU[t], 0);
        __half* hprev = ((t - 1) & 1) ? pH1 : pH0;
        __half* hnext = (t & 1) ? pH1 : pH0;
        urec<<<dim3(N3 / BN, BATCH / 128), 256, SMEM_REC>>>(
            hprev, pWr, hnext, pU + (size_t)t * BATCH * N3, nullptr);
    }

    // final FC
    final_k<<<BATCH, 256>>>(pH1, Wfc, bfc, (float*)d_out);
}